// round 5
// baseline (speedup 1.0000x reference)
#include <cuda_runtime.h>
#include <math.h>

// x [L=4096, B=4, D=1024] fp32, channel-contiguous (BD = 4096 per timestep)
#define L   4096
#define B   4
#define D   1024
#define BD  (B * D)        // 4096 channels
#define C   256            // time chunks
#define LC  (L / C)        // 16 steps per chunk
#define V8  (BD / 8)       // 512 8-channel groups per timestep
#define DV8 (D / 8)        // 128 groups per D

// Per-channel coefficients
__device__ float g_cr[D], g_ci[D];     // c
__device__ float g_Ar[D], g_Ai[D];     // c^LC
// Chunk end-states (zero-init local scans) and true entering prefixes,
// [chunk][bd] layout so K1/K3 8-wide accesses are contiguous. 4 MB each.
__device__ float g_er[C * BD], g_ei[C * BD];
__device__ float g_pr[C * BD], g_pi[C * BD];

struct F8 { float v[8]; };

__device__ __forceinline__ F8 ld8_evict_last(const float* p) {
    unsigned r0, r1, r2, r3, r4, r5, r6, r7;
    asm volatile("ld.global.nc.L2::evict_last.v8.b32 "
                 "{%0,%1,%2,%3,%4,%5,%6,%7}, [%8];"
                 : "=r"(r0), "=r"(r1), "=r"(r2), "=r"(r3),
                   "=r"(r4), "=r"(r5), "=r"(r6), "=r"(r7)
                 : "l"(p));
    F8 f;
    f.v[0]=__uint_as_float(r0); f.v[1]=__uint_as_float(r1);
    f.v[2]=__uint_as_float(r2); f.v[3]=__uint_as_float(r3);
    f.v[4]=__uint_as_float(r4); f.v[5]=__uint_as_float(r5);
    f.v[6]=__uint_as_float(r6); f.v[7]=__uint_as_float(r7);
    return f;
}
__device__ __forceinline__ F8 ld8_evict_first(const float* p) {
    unsigned r0, r1, r2, r3, r4, r5, r6, r7;
    asm volatile("ld.global.nc.L2::evict_first.v8.b32 "
                 "{%0,%1,%2,%3,%4,%5,%6,%7}, [%8];"
                 : "=r"(r0), "=r"(r1), "=r"(r2), "=r"(r3),
                   "=r"(r4), "=r"(r5), "=r"(r6), "=r"(r7)
                 : "l"(p));
    F8 f;
    f.v[0]=__uint_as_float(r0); f.v[1]=__uint_as_float(r1);
    f.v[2]=__uint_as_float(r2); f.v[3]=__uint_as_float(r3);
    f.v[4]=__uint_as_float(r4); f.v[5]=__uint_as_float(r5);
    f.v[6]=__uint_as_float(r6); f.v[7]=__uint_as_float(r7);
    return f;
}

// ---------------------------------------------------------------------------
// K0: per-channel coefficients in double precision.
// ---------------------------------------------------------------------------
__global__ void k0_coeffs(const float* __restrict__ lmlg,
                          const float* __restrict__ theta) {
    int d = blockIdx.x * blockDim.x + threadIdx.x;
    if (d >= D) return;
    double g  = exp(-exp((double)lmlg[d]));
    double th = (double)theta[d];
    double cr = g * cos(th);
    double ci = g * sin(th);
    g_cr[d] = (float)cr;
    g_ci[d] = (float)ci;
    // c^16 via 4 squarings in double
    double ar = cr, ai = ci;
#pragma unroll
    for (int i = 0; i < 4; i++) {
        double nr = ar * ar - ai * ai;
        double ni = 2.0 * ar * ai;
        ar = nr; ai = ni;
    }
    g_Ar[d] = (float)ar;
    g_Ai[d] = (float)ai;
}

// ---------------------------------------------------------------------------
// K1: local scan per (chunk, 8-channel group), zero init; store end state.
// 131072 threads -> 512 CTAs.
// ---------------------------------------------------------------------------
__global__ void __launch_bounds__(256) k1_local_end(const float* __restrict__ x) {
    int tid = blockIdx.x * blockDim.x + threadIdx.x;    // C*V8 = 131072
    int chunk = tid >> 9;            // / V8
    int v     = tid & (V8 - 1);
    int dbase = (v & (DV8 - 1)) * 8;
    float cr[8], ci[8], sr[8], si[8];
#pragma unroll
    for (int k = 0; k < 8; k++) {
        cr[k] = g_cr[dbase + k];
        ci[k] = g_ci[dbase + k];
        sr[k] = 0.f; si[k] = 0.f;
    }
    const float* xp = x + (size_t)chunk * LC * BD + v * 8;
#pragma unroll
    for (int n = 0; n < LC; n++) {
        F8 xv = ld8_evict_last(xp + (size_t)n * BD);
#pragma unroll
        for (int k = 0; k < 8; k++) {
            float nr = fmaf(cr[k], sr[k], fmaf(-ci[k], si[k], xv.v[k]));
            float ni = fmaf(ci[k], sr[k], cr[k] * si[k]);
            sr[k] = nr; si[k] = ni;
        }
    }
    size_t so = (size_t)chunk * BD + v * 8;
    *(float4*)(g_er + so)     = make_float4(sr[0], sr[1], sr[2], sr[3]);
    *(float4*)(g_er + so + 4) = make_float4(sr[4], sr[5], sr[6], sr[7]);
    *(float4*)(g_ei + so)     = make_float4(si[0], si[1], si[2], si[3]);
    *(float4*)(g_ei + so + 4) = make_float4(si[4], si[5], si[6], si[7]);
}

// ---------------------------------------------------------------------------
// K2: serial scan over the C=256 chunk boundaries per channel.
// ---------------------------------------------------------------------------
__global__ void k2_chunk_scan(const float* __restrict__ last_conv_init) {
    int bd = blockIdx.x * blockDim.x + threadIdx.x;
    if (bd >= BD) return;
    int d = bd & (D - 1);
    float Ar = g_Ar[d], Ai = g_Ai[d];
    float sr = last_conv_init[d], si = 0.f;
    g_pr[bd] = sr; g_pi[bd] = si;
#pragma unroll 8
    for (int j = 0; j < C - 1; j++) {
        float e_r = g_er[j * BD + bd], e_i = g_ei[j * BD + bd];
        float nr = fmaf(Ar, sr, fmaf(-Ai, si, e_r));
        float ni = fmaf(Ai, sr, fmaf(Ar, si, e_i));
        sr = nr; si = ni;
        g_pr[(j + 1) * BD + bd] = sr;
        g_pi[(j + 1) * BD + bd] = si;
    }
}

// ---------------------------------------------------------------------------
// K3: replay seeded with true prefix, out = Re(s)*x. Streaming stores.
// ---------------------------------------------------------------------------
__global__ void __launch_bounds__(256) k3_finalize(const float* __restrict__ x,
                                                   float* __restrict__ out) {
    int tid = blockIdx.x * blockDim.x + threadIdx.x;
    int chunk = tid >> 9;
    int v     = tid & (V8 - 1);
    int dbase = (v & (DV8 - 1)) * 8;
    float cr[8], ci[8], sr[8], si[8];
    size_t so = (size_t)chunk * BD + v * 8;
    float4 p0 = *(const float4*)(g_pr + so);
    float4 p1 = *(const float4*)(g_pr + so + 4);
    float4 q0 = *(const float4*)(g_pi + so);
    float4 q1 = *(const float4*)(g_pi + so + 4);
    sr[0]=p0.x; sr[1]=p0.y; sr[2]=p0.z; sr[3]=p0.w;
    sr[4]=p1.x; sr[5]=p1.y; sr[6]=p1.z; sr[7]=p1.w;
    si[0]=q0.x; si[1]=q0.y; si[2]=q0.z; si[3]=q0.w;
    si[4]=q1.x; si[5]=q1.y; si[6]=q1.z; si[7]=q1.w;
#pragma unroll
    for (int k = 0; k < 8; k++) {
        cr[k] = g_cr[dbase + k];
        ci[k] = g_ci[dbase + k];
    }
    size_t base = (size_t)chunk * LC * BD + v * 8;
    const float* xp = x + base;
    float*       op = out + base;
#pragma unroll
    for (int n = 0; n < LC; n++) {
        F8 xv = ld8_evict_first(xp + (size_t)n * BD);
        float o[8];
#pragma unroll
        for (int k = 0; k < 8; k++) {
            float nr = fmaf(cr[k], sr[k], fmaf(-ci[k], si[k], xv.v[k]));
            float ni = fmaf(ci[k], sr[k], cr[k] * si[k]);
            sr[k] = nr; si[k] = ni;
            o[k] = nr * xv.v[k];
        }
        __stcs((float4*)(op + (size_t)n * BD),
               make_float4(o[0], o[1], o[2], o[3]));
        __stcs((float4*)(op + (size_t)n * BD + 4),
               make_float4(o[4], o[5], o[6], o[7]));
    }
}

// ---------------------------------------------------------------------------
extern "C" void kernel_launch(void* const* d_in, const int* in_sizes, int n_in,
                              void* d_out, int out_size) {
    const float* x    = (const float*)d_in[0];  // [L,B,D]
    const float* lmlg = (const float*)d_in[1];  // [D]
    const float* th   = (const float*)d_in[2];  // [D]
    const float* lci  = (const float*)d_in[3];  // [D]
    float* out = (float*)d_out;

    k0_coeffs<<<(D + 255) / 256, 256>>>(lmlg, th);
    k1_local_end<<<(C * V8) / 256, 256>>>(x);
    k2_chunk_scan<<<(BD + 255) / 256, 256>>>(lci);
    k3_finalize<<<(C * V8) / 256, 256>>>(x, out);
}

// round 6
// speedup vs baseline: 1.1928x; 1.1928x over previous
#include <cuda_runtime.h>
#include <math.h>

// x [L=4096, B=4, D=1024] fp32, channel-contiguous (BD = 4096 per timestep)
#define L      4096
#define B      4
#define D      1024
#define BD     (B * D)       // 4096 channels
#define T      32            // timesteps per chunk
#define NCHUNK (L / T)       // 128 chunks
#define CBLK   256           // channels per CTA
#define NCB    (BD / CBLK)   // 16 channel-blocks

// Coefficients: c and a = c^T
__device__ float g_cr[D], g_ci[D], g_ar[D], g_ai[D];
// Spine: per-channel aggregates (zero-init chunk exit) and inclusive (true exit)
__device__ float2 g_agg[NCHUNK * BD];    // 4 MB
__device__ float2 g_incl[NCHUNK * BD];   // 4 MB
// Per-(chunk, chanblock) status: 0 = none, 1 = agg ready, 2 = incl ready
__device__ int g_flag[NCHUNK * NCB];

__device__ __forceinline__ int ld_acquire(const int* p) {
    int v;
    asm volatile("ld.global.acquire.gpu.b32 %0, [%1];" : "=r"(v) : "l"(p));
    return v;
}
__device__ __forceinline__ void st_release(int* p, int v) {
    asm volatile("st.global.release.gpu.b32 [%0], %1;" :: "l"(p), "r"(v));
}

// ---------------------------------------------------------------------------
// K0: coefficients (double precision) + flag reset (every launch).
// 4096 threads: tid<1024 -> coeffs; tid<2048 -> zero flags.
// ---------------------------------------------------------------------------
__global__ void k0_setup(const float* __restrict__ lmlg,
                         const float* __restrict__ theta) {
    int t = blockIdx.x * blockDim.x + threadIdx.x;
    if (t < NCHUNK * NCB) g_flag[t] = 0;
    if (t < D) {
        double g  = exp(-exp((double)lmlg[t]));
        double th = (double)theta[t];
        double cr = g * cos(th);
        double ci = g * sin(th);
        g_cr[t] = (float)cr;
        g_ci[t] = (float)ci;
        double ar = cr, ai = ci;           // a = c^32 : 5 squarings
#pragma unroll
        for (int i = 0; i < 5; i++) {
            double nr = ar * ar - ai * ai;
            double ni = 2.0 * ar * ai;
            ar = nr; ai = ni;
        }
        g_ar[t] = (float)ar;
        g_ai[t] = (float)ai;
    }
}

// ---------------------------------------------------------------------------
// K1: single-pass scan with decoupled lookback.
// bid = chunk*NCB + cb  (chunk-major so predecessors are scheduled first)
// ---------------------------------------------------------------------------
__global__ void __launch_bounds__(CBLK)
k1_scan(const float* __restrict__ x,
        const float* __restrict__ last_conv_init,
        float* __restrict__ out) {
    int bid   = blockIdx.x;
    int chunk = bid >> 4;              // / NCB
    int cb    = bid & (NCB - 1);
    int tid   = threadIdx.x;
    int ch    = cb * CBLK + tid;       // global channel 0..4095
    int d     = ch & (D - 1);

    float cr = g_cr[d], ci = g_ci[d];
    float ar = g_ar[d], ai = g_ai[d];

    // ---- load tile into registers (32 independent coalesced loads) ----
    float xr[T];
    const float* xp = x + (size_t)chunk * T * BD + ch;
#pragma unroll
    for (int n = 0; n < T; n++)
        xr[n] = __ldg(xp + (size_t)n * BD);

    // ---- local zero-init scan -> aggregate E ----
    float sr = 0.f, si = 0.f;
#pragma unroll
    for (int n = 0; n < T; n++) {
        float nr = fmaf(cr, sr, fmaf(-ci, si, xr[n]));
        float ni = fmaf(ci, sr, cr * si);
        sr = nr; si = ni;
    }

    // ---- publish aggregate ----
    size_t sidx = (size_t)chunk * BD + ch;
    g_agg[sidx] = make_float2(sr, si);
    __threadfence();
    __syncthreads();
    if (tid == 0) st_release(&g_flag[chunk * NCB + cb], 1);

    // ---- lookback: resolve entering prefix (per-thread, channels indep.) ----
    float pr, pi;
    if (chunk == 0) {
        pr = last_conv_init[d];
        pi = 0.f;
    } else {
        float accR = 0.f, accI = 0.f;   // sum of a^k * E terms
        float pwR = 1.f, pwI = 0.f;     // a^(m-1-j)
        int j = chunk - 1;
        for (;;) {
            int f;
            const int* fp = &g_flag[j * NCB + cb];
            while ((f = ld_acquire(fp)) == 0) __nanosleep(20);
            if (f == 2) {
                float2 v = g_incl[(size_t)j * BD + ch];
                pr = fmaf(pwR, v.x, fmaf(-pwI, v.y, accR));
                pi = fmaf(pwR, v.y, fmaf(pwI, v.x, accI));
                break;
            }
            // aggregate only: fold E_j, advance power, step back
            float2 e = g_agg[(size_t)j * BD + ch];
            accR = fmaf(pwR, e.x, fmaf(-pwI, e.y, accR));
            accI = fmaf(pwR, e.y, fmaf(pwI, e.x, accI));
            float t = pwR * ar - pwI * ai;
            pwI = pwR * ai + pwI * ar;
            pwR = t;
            if (j == 0) {               // consumed chunk 0: apply seed
                float s0 = last_conv_init[d];
                pr = fmaf(pwR, s0, accR);
                pi = fmaf(pwI, s0, accI);
                break;
            }
            j--;
        }
    }

    // ---- publish inclusive state (exit = a*prefix + E) ASAP ----
    float exR = fmaf(ar, pr, fmaf(-ai, pi, sr));
    float exI = fmaf(ai, pr, fmaf(ar, pi, si));
    g_incl[sidx] = make_float2(exR, exI);
    __threadfence();
    __syncthreads();
    if (tid == 0) st_release(&g_flag[chunk * NCB + cb], 2);

    // ---- replay from registers, write out = Re(s) * x ----
    sr = pr; si = pi;
    float* op = out + (size_t)chunk * T * BD + ch;
#pragma unroll
    for (int n = 0; n < T; n++) {
        float nr = fmaf(cr, sr, fmaf(-ci, si, xr[n]));
        float ni = fmaf(ci, sr, cr * si);
        sr = nr; si = ni;
        __stcs(op + (size_t)n * BD, nr * xr[n]);
    }
}

// ---------------------------------------------------------------------------
extern "C" void kernel_launch(void* const* d_in, const int* in_sizes, int n_in,
                              void* d_out, int out_size) {
    const float* x    = (const float*)d_in[0];  // [L,B,D]
    const float* lmlg = (const float*)d_in[1];  // [D]
    const float* th   = (const float*)d_in[2];  // [D]
    const float* lci  = (const float*)d_in[3];  // [D]
    float* out = (float*)d_out;

    k0_setup<<<16, 256>>>(lmlg, th);
    k1_scan<<<NCHUNK * NCB, CBLK>>>(x, lci, out);
}